// round 12
// baseline (speedup 1.0000x reference)
#include <cuda_runtime.h>
#include <cstdint>
#include <cstddef>

#define WIDTH  2048
#define DEPTH  8
#define DP1    9
#define TMOD   242          // 30*DEPTH + 2
#define WD     16384        // WIDTH*DEPTH
#define NSPLIT 16           // i-splits for hidden
#define CHUNK  128          // WIDTH / NSPLIT
#define HBLK   256          // hidden blocks (16 kblk x 16 split)
#define WROLE  (HBLK + WIDTH)       // 2304 W-role blocks
#define MAIN_BLK (WROLE * 3)        // 6912: bx%3==0 -> W-role, else saog
#define SPLIT_GROUP 144             // 16 hidden + 128 contrib per split

// d_out layout (float32, reference return order)
#define OFF_OUT   0ULL
#define OFF_STATE 1ULL
#define OFF_SA    18433ULL
#define OFF_SG    4478977ULL
#define OFF_OG    4495361ULL
#define OFF_GRAD  8955905ULL
#define OFF_OWG   42510337ULL

#define N_SAOG    (WIDTH * DP1 * TMOD)     // 4460544
#define NQ_SAOG   1115135                  // quads idx = 3+4q
#define NQ_GROW   4095                     // per-row quads k = 3+4q

// scratch (allocation-free)
__device__ float g_hpart[NSPLIT][WD];     // hidden partials (1 MB)
__device__ float g_contrib[WD];           // contrib[i*8+a], a=0..6
__device__ float g_m[WD];
__device__ float g_mshift[WD];            // g_mshift[t] = m[t+3]
__device__ float g_aprev[WD];
__device__ float g_out_acc;

__device__ __forceinline__ int posmod(int v, int m) {
    int r = v % m;
    return r < 0 ? r + m : r;
}

// ---------------------------------------------------------------------------
// MAIN: W-roles ordered SPLIT-MAJOR so hidden blocks and contrib rows for the
// SAME 128 W rows are co-resident -> full L2 dedup of the second W read.
// bx%3==0 -> W-role wr=bx/3: split s=wr/144; local<16 -> hidden(kblk=local,s);
// else contrib row i = s*128 + local-16.  bx%3!=0 -> saog pure copy
// (no time logic; finalize overwrites the time slice afterwards).
// ---------------------------------------------------------------------------
__global__ void k_main(const float* __restrict__ W,
                       const float* __restrict__ state_in,
                       const float* __restrict__ sgrad,
                       float* __restrict__ out,
                       const float* __restrict__ sa_in,
                       const float* __restrict__ og_in) {
    __shared__ float sh[CHUNK * 8];
    const int tid = threadIdx.x;
    const int bx  = blockIdx.x;

    if (bx % 3 == 0) {
        const int wr = bx / 3;             // 0..2303
        if (wr == 0 && tid == 0) g_out_acc = 0.f;
        const int split = wr / SPLIT_GROUP;
        const int local = wr - split * SPLIT_GROUP;

        if (local < 16) {
            // ---- hidden partial: hidden[k] = sum_i W[i*WD+k]*state[i,k&7]
            const int kblk = local;
            const int k4 = kblk * 1024 + tid * 4;
            const int i0 = split * CHUNK;
            const int dbase = (tid & 1) * 4;

            for (int idx = tid; idx < CHUNK * 8; idx += 256) {
                int i = idx >> 3, d = idx & 7;
                sh[idx] = state_in[(size_t)(i0 + i) * DP1 + d];
            }
            __syncthreads();

            const float* Wp = W + (size_t)i0 * WD + k4;
            float4 acc = make_float4(0.f, 0.f, 0.f, 0.f);
#pragma unroll 8
            for (int i = 0; i < CHUNK; ++i) {
                float4 w4 = *reinterpret_cast<const float4*>(Wp + (size_t)i * WD);
                float4 sv = *reinterpret_cast<const float4*>(&sh[i * 8 + dbase]);
                acc.x = fmaf(w4.x, sv.x, acc.x);
                acc.y = fmaf(w4.y, sv.y, acc.y);
                acc.z = fmaf(w4.z, sv.z, acc.z);
                acc.w = fmaf(w4.w, sv.w, acc.w);
            }
            *reinterpret_cast<float4*>(&g_hpart[split][k4]) = acc;
        } else {
            // ---- contrib[i,a] = sum_j W[i,j,a+1]*sgrad[j,a+1], a=0..6
            const int i = split * CHUNK + (local - 16);
            const float4* Wr = reinterpret_cast<const float4*>(W + (size_t)i * WD);
            const float4* gg = reinterpret_cast<const float4*>(sgrad);

            float acc[7] = {0, 0, 0, 0, 0, 0, 0};
            for (int j = tid; j < WIDTH; j += 256) {
                float4 w0 = Wr[j * 2];
                float4 w1 = Wr[j * 2 + 1];
                float4 g0 = gg[j * 2];
                float4 g1 = gg[j * 2 + 1];
                acc[0] = fmaf(w0.y, g0.y, acc[0]);
                acc[1] = fmaf(w0.z, g0.z, acc[1]);
                acc[2] = fmaf(w0.w, g0.w, acc[2]);
                acc[3] = fmaf(w1.x, g1.x, acc[3]);
                acc[4] = fmaf(w1.y, g1.y, acc[4]);
                acc[5] = fmaf(w1.z, g1.z, acc[5]);
                acc[6] = fmaf(w1.w, g1.w, acc[6]);
            }
            float (*red)[7] = reinterpret_cast<float (*)[7]>(sh);
#pragma unroll
            for (int a = 0; a < 7; ++a)
#pragma unroll
                for (int off = 16; off; off >>= 1)
                    acc[a] += __shfl_down_sync(0xffffffffu, acc[a], off);
            if ((tid & 31) == 0) {
                int w = tid >> 5;
#pragma unroll
                for (int a = 0; a < 7; ++a) red[w][a] = acc[a];
            }
            __syncthreads();
            if (tid < 7) {
                float s = 0.f;
#pragma unroll
                for (int w = 0; w < 8; ++w) s += red[w][tid];
                g_contrib[(size_t)i * 8 + tid] = s;
            }
        }
    } else {
        // ---- saog: pure dual copy, sector-aligned stores (quad idx = 3+4q).
        const int sid = bx - bx / 3 - 1;   // 0..4607
        const int q = sid * 256 + tid;
        if (q >= NQ_SAOG) return;
        const int idx = 3 + 4 * q;

        const float4* sa4 = reinterpret_cast<const float4*>(sa_in);
        const float4* og4 = reinterpret_cast<const float4*>(og_in);
        float4 sA = __ldcs(sa4 + q), sB = __ldcs(sa4 + q + 1);
        float4 oA = __ldcs(og4 + q), oB = __ldcs(og4 + q + 1);

        *reinterpret_cast<float4*>(&out[OFF_SA + idx]) =
            make_float4(sA.w, sB.x, sB.y, sB.z);
        *reinterpret_cast<float4*>(&out[OFF_OG + idx]) =
            make_float4(oA.w, oB.x, oB.y, oB.z);

        if (q == 0) {
#pragma unroll
            for (int e = 0; e < 3; ++e) {
                out[OFF_SA + e] = sa_in[e];
                out[OFF_OG + e] = og_in[e];
            }
        }
        if (q == NQ_SAOG - 1) {
            out[OFF_SA + N_SAOG - 1] = sa_in[N_SAOG - 1];
            out[OFF_OG + N_SAOG - 1] = og_in[N_SAOG - 1];
        }
    }
}

// ---------------------------------------------------------------------------
// finalize — state/owg, output dot, full sg logic, m / m-shift / aprev,
// plus the sa/og time-slice overwrite (k_main copied stale values there).
// tia(a) = time + 2a - 14 (mod 242); tia==time only at a=7, (tia±1)!=time
// for all a -> all sa/og reads at a<7 hit the ORIGINAL arrays; at a=7 the
// only aliased read is this thread's own fresh state value.
// ---------------------------------------------------------------------------
__global__ void k_finalize(float* __restrict__ out,
                           const float* __restrict__ x,
                           const float* __restrict__ ow,
                           const float* __restrict__ sa_in,
                           const float* __restrict__ og_in,
                           const int* __restrict__ time_p) {
    const int k = blockIdx.x * blockDim.x + threadIdx.x;   // 0..WD-1
    const int w = k >> 3, a = k & 7;
    const int time = *time_p;

    float h = 0.f;
#pragma unroll
    for (int c = 0; c < NSPLIT; ++c) h += g_hpart[c][k];
    float s = fmaxf(h, 0.f);

    size_t o = (size_t)w * DP1 + a + 1;
    out[OFF_STATE + o] = s;
    out[OFF_OWG + o]   = s;
    out[OFF_SA + o * TMOD + time] = s;
    out[OFF_OG + o * TMOD + time] = ow[o];
    float v = ow[o] * s;
    if (a == 0) {
        float xv = x[w];
        size_t o0 = (size_t)w * DP1;
        out[OFF_STATE + o0] = xv;
        out[OFF_OWG   + o0] = xv;
        out[OFF_SA + o0 * TMOD + time] = xv;
        out[OFF_OG + o0 * TMOD + time] = ow[o0];
        v = fmaf(ow[o0], xv, v);
    }

    const int tia = posmod(time - 2 * DEPTH + 2 * (a + 1), TMOD);
    float sgv, rg, aprev;
    if (a < DEPTH - 1) {
        int t1 = (tia + 1) % TMOD;
        float rmv = sa_in[((size_t)w * DP1 + a + 2) * TMOD + t1];
        sgv = fmaf(rmv > 0.f ? 1.f : 0.f, g_contrib[k],
                   og_in[((size_t)w * DP1 + a + 1) * TMOD + tia]);
        rg = (sa_in[((size_t)w * DP1 + a + 1) * TMOD + tia] > 0.f) ? 1.f : 0.f;
        aprev = sa_in[((size_t)w * DP1 + a) * TMOD + posmod(tia - 1, TMOD)];
    } else {
        sgv = ow[(size_t)w * DP1 + DEPTH];
        rg = (s > 0.f) ? 1.f : 0.f;
        aprev = sa_in[((size_t)w * DP1 + DEPTH - 1) * TMOD + posmod(time - 1, TMOD)];
    }
    out[OFF_SG + k] = sgv;
    float mval = sgv * rg;
    g_m[k] = mval;
    if (k >= 3) g_mshift[k - 3] = mval;
    g_aprev[k] = aprev;

    __shared__ float red[8];
#pragma unroll
    for (int off = 16; off; off >>= 1)
        v += __shfl_down_sync(0xffffffffu, v, off);
    if ((threadIdx.x & 31) == 0) red[threadIdx.x >> 5] = v;
    __syncthreads();
    if (threadIdx.x == 0) {
        float t = 0.f;
#pragma unroll
        for (int i = 0; i < 8; ++i) t += red[i];
        atomicAdd(&g_out_acc, t);
    }
}

// ---------------------------------------------------------------------------
// grad: 2 rows per block, warp = (row, 16KB span). Each warp writes ONE
// sequential 16KB stream; the two rows' span-mates share the SM so the second
// m-span read hits L1 -> m L2 traffic halves vs block-per-row.
// Quad q covers k = 4q+3..4q+6; d-pattern by q parity (= lane parity).
// ---------------------------------------------------------------------------
__global__ void k_grad(float* __restrict__ out) {
    const int tid = threadIdx.x;
    const int wid = tid >> 5, lane = tid & 31;
    const int r    = wid & 1;          // row within pair
    const int span = wid >> 1;         // 0..3 (1024 quads each)
    const int i = blockIdx.x * 2 + r;

    if (blockIdx.x == 0 && tid == 0) out[OFF_OUT] = g_out_acc;

    const float* ap = g_aprev + (size_t)i * 8;
    const float4 apv = (lane & 1)
        ? make_float4(__ldg(ap + 7), __ldg(ap + 0), __ldg(ap + 1), __ldg(ap + 2))
        : make_float4(__ldg(ap + 3), __ldg(ap + 4), __ldg(ap + 5), __ldg(ap + 6));

    float* dst = out + OFF_GRAD + (size_t)i * WD;
    const float4* ms4 = reinterpret_cast<const float4*>(g_mshift);
    const int qbase = span * 1024 + lane;

#pragma unroll 8
    for (int it = 0; it < 32; ++it) {
        const int q = qbase + it * 32;
        if (q < NQ_GROW) {
            float4 mv = __ldg(ms4 + q);
            *reinterpret_cast<float4*>(dst + 3 + 4 * q) =
                make_float4(apv.x * mv.x, apv.y * mv.y,
                            apv.z * mv.z, apv.w * mv.w);
        }
    }

    // head (k=0,1,2) and tail (k=WD-1) for both rows of the pair
    if (tid < 2) {
        const int ii = blockIdx.x * 2 + tid;
        const float* app = g_aprev + (size_t)ii * 8;
        float* d = out + OFF_GRAD + (size_t)ii * WD;
        d[0] = __ldg(app + 0) * g_m[0];
        d[1] = __ldg(app + 1) * g_m[1];
        d[2] = __ldg(app + 2) * g_m[2];
    } else if (tid < 4) {
        const int ii = blockIdx.x * 2 + (tid - 2);
        const float* app = g_aprev + (size_t)ii * 8;
        float* d = out + OFF_GRAD + (size_t)ii * WD;
        d[WD - 1] = __ldg(app + 7) * g_m[WD - 1];
    }
}

// ---------------------------------------------------------------------------
extern "C" void kernel_launch(void* const* d_in, const int* in_sizes, int n_in,
                              void* d_out, int out_size) {
    const float* x    = (const float*)d_in[0];
    const float* W    = (const float*)d_in[1];
    const float* ow   = (const float*)d_in[2];
    const float* st   = (const float*)d_in[3];
    const float* sa   = (const float*)d_in[4];
    const float* sgr  = (const float*)d_in[5];
    const float* og   = (const float*)d_in[6];
    const int*   tim  = (const int*)d_in[7];
    float* out = (float*)d_out;

    k_main<<<MAIN_BLK, 256>>>(W, st, sgr, out, sa, og);
    k_finalize<<<WD / 256, 256>>>(out, x, ow, sa, og, tim);
    k_grad<<<WIDTH / 2, 256>>>(out);
}

// round 13
// speedup vs baseline: 1.0541x; 1.0541x over previous
#include <cuda_runtime.h>
#include <cstdint>
#include <cstddef>

#define WIDTH  2048
#define DEPTH  8
#define DP1    9
#define TMOD   242          // 30*DEPTH + 2
#define WD     16384        // WIDTH*DEPTH
#define NSPLIT 16           // i-splits for hidden
#define CHUNK  128          // WIDTH / NSPLIT
#define HBLK   256          // hidden blocks (16 kblk x 16 split)
#define WROLE  (HBLK + WIDTH)       // 2304 W-role blocks
#define MAIN_BLK (WROLE * 3)        // 6912: bx%3==0 -> W-role, else saog

// d_out layout (float32, reference return order)
#define OFF_OUT   0ULL
#define OFF_STATE 1ULL
#define OFF_SA    18433ULL
#define OFF_SG    4478977ULL
#define OFF_OG    4495361ULL
#define OFF_GRAD  8955905ULL
#define OFF_OWG   42510337ULL

#define N_SAOG    (WIDTH * DP1 * TMOD)     // 4460544
#define NQ_SAOG   1115135                  // quads idx = 3+4q
#define NQ_GROW   4095                     // per-row quads k = 3+4q

// scratch (allocation-free)
__device__ float g_hpart[NSPLIT][WD];     // hidden partials (1 MB)
__device__ float g_contrib[WD];           // contrib[i*8+a], a=0..6
__device__ float g_m[WD];
__device__ float g_mshift[WD];            // g_mshift[t] = m[t+3]
__device__ float g_aprev[WD];
__device__ float g_out_acc;

__device__ __forceinline__ int posmod(int v, int m) {
    int r = v % m;
    return r < 0 ? r + m : r;
}

// ---------------------------------------------------------------------------
// MAIN (round-11 structure): bx%3==0 -> W-role in round-8 order (wr<256
// hidden, else contrib row wr-256); bx%3!=0 -> saog pure copy.
// saog uses __ldcs loads AND __stcs stores so the copy stream neither reads
// into nor write-allocates L2 — protecting the W working set (134 MB ~ L2
// capacity) that the two reduction roles dedup on.
// ---------------------------------------------------------------------------
__global__ void k_main(const float* __restrict__ W,
                       const float* __restrict__ state_in,
                       const float* __restrict__ sgrad,
                       float* __restrict__ out,
                       const float* __restrict__ sa_in,
                       const float* __restrict__ og_in) {
    __shared__ float sh[CHUNK * 8];
    const int tid = threadIdx.x;
    const int bx  = blockIdx.x;

    if (bx % 3 == 0) {
        const int wr = bx / 3;             // 0..2303, round-8 relative order
        if (wr == 0 && tid == 0) g_out_acc = 0.f;

        if (wr < HBLK) {
            // ---- hidden partial: hidden[k] = sum_i W[i*WD+k]*state[i,k&7]
            const int kblk  = wr & 15;
            const int split = wr >> 4;
            const int k4 = kblk * 1024 + tid * 4;
            const int i0 = split * CHUNK;
            const int dbase = (tid & 1) * 4;

            for (int idx = tid; idx < CHUNK * 8; idx += 256) {
                int i = idx >> 3, d = idx & 7;
                sh[idx] = state_in[(size_t)(i0 + i) * DP1 + d];
            }
            __syncthreads();

            const float* Wp = W + (size_t)i0 * WD + k4;
            float4 acc = make_float4(0.f, 0.f, 0.f, 0.f);
#pragma unroll 8
            for (int i = 0; i < CHUNK; ++i) {
                float4 w4 = *reinterpret_cast<const float4*>(Wp + (size_t)i * WD);
                float4 sv = *reinterpret_cast<const float4*>(&sh[i * 8 + dbase]);
                acc.x = fmaf(w4.x, sv.x, acc.x);
                acc.y = fmaf(w4.y, sv.y, acc.y);
                acc.z = fmaf(w4.z, sv.z, acc.z);
                acc.w = fmaf(w4.w, sv.w, acc.w);
            }
            *reinterpret_cast<float4*>(&g_hpart[split][k4]) = acc;
        } else {
            // ---- contrib[i,a] = sum_j W[i,j,a+1]*sgrad[j,a+1], a=0..6
            const int i = wr - HBLK;
            const float4* Wr = reinterpret_cast<const float4*>(W + (size_t)i * WD);
            const float4* gg = reinterpret_cast<const float4*>(sgrad);

            float acc[7] = {0, 0, 0, 0, 0, 0, 0};
            for (int j = tid; j < WIDTH; j += 256) {
                float4 w0 = Wr[j * 2];
                float4 w1 = Wr[j * 2 + 1];
                float4 g0 = gg[j * 2];
                float4 g1 = gg[j * 2 + 1];
                acc[0] = fmaf(w0.y, g0.y, acc[0]);
                acc[1] = fmaf(w0.z, g0.z, acc[1]);
                acc[2] = fmaf(w0.w, g0.w, acc[2]);
                acc[3] = fmaf(w1.x, g1.x, acc[3]);
                acc[4] = fmaf(w1.y, g1.y, acc[4]);
                acc[5] = fmaf(w1.z, g1.z, acc[5]);
                acc[6] = fmaf(w1.w, g1.w, acc[6]);
            }
            float (*red)[7] = reinterpret_cast<float (*)[7]>(sh);
#pragma unroll
            for (int a = 0; a < 7; ++a)
#pragma unroll
                for (int off = 16; off; off >>= 1)
                    acc[a] += __shfl_down_sync(0xffffffffu, acc[a], off);
            if ((tid & 31) == 0) {
                int w = tid >> 5;
#pragma unroll
                for (int a = 0; a < 7; ++a) red[w][a] = acc[a];
            }
            __syncthreads();
            if (tid < 7) {
                float s = 0.f;
#pragma unroll
                for (int w = 0; w < 8; ++w) s += red[w][tid];
                g_contrib[(size_t)i * 8 + tid] = s;
            }
        }
    } else {
        // ---- saog: pure dual copy, streaming both directions.
        const int sid = bx - bx / 3 - 1;   // 0..4607
        const int q = sid * 256 + tid;
        if (q >= NQ_SAOG) return;
        const int idx = 3 + 4 * q;

        const float4* sa4 = reinterpret_cast<const float4*>(sa_in);
        const float4* og4 = reinterpret_cast<const float4*>(og_in);
        float4 sA = __ldcs(sa4 + q), sB = __ldcs(sa4 + q + 1);
        float4 oA = __ldcs(og4 + q), oB = __ldcs(og4 + q + 1);

        __stcs(reinterpret_cast<float4*>(&out[OFF_SA + idx]),
               make_float4(sA.w, sB.x, sB.y, sB.z));
        __stcs(reinterpret_cast<float4*>(&out[OFF_OG + idx]),
               make_float4(oA.w, oB.x, oB.y, oB.z));

        if (q == 0) {
#pragma unroll
            for (int e = 0; e < 3; ++e) {
                out[OFF_SA + e] = sa_in[e];
                out[OFF_OG + e] = og_in[e];
            }
        }
        if (q == NQ_SAOG - 1) {
            out[OFF_SA + N_SAOG - 1] = sa_in[N_SAOG - 1];
            out[OFF_OG + N_SAOG - 1] = og_in[N_SAOG - 1];
        }
    }
}

// ---------------------------------------------------------------------------
// finalize — state/owg, output dot, full sg logic, m / m-shift / aprev,
// plus the sa/og time-slice overwrite (k_main copied stale values there).
// tia(a) = time + 2a - 14 (mod 242); tia==time only at a=7, (tia±1)!=time
// for all a -> all sa/og reads at a<7 hit the ORIGINAL arrays; at a=7 the
// only aliased read is this thread's own fresh state value.
// ---------------------------------------------------------------------------
__global__ void k_finalize(float* __restrict__ out,
                           const float* __restrict__ x,
                           const float* __restrict__ ow,
                           const float* __restrict__ sa_in,
                           const float* __restrict__ og_in,
                           const int* __restrict__ time_p) {
    const int k = blockIdx.x * blockDim.x + threadIdx.x;   // 0..WD-1
    const int w = k >> 3, a = k & 7;
    const int time = *time_p;

    float h = 0.f;
#pragma unroll
    for (int c = 0; c < NSPLIT; ++c) h += g_hpart[c][k];
    float s = fmaxf(h, 0.f);

    size_t o = (size_t)w * DP1 + a + 1;
    out[OFF_STATE + o] = s;
    out[OFF_OWG + o]   = s;
    out[OFF_SA + o * TMOD + time] = s;
    out[OFF_OG + o * TMOD + time] = ow[o];
    float v = ow[o] * s;
    if (a == 0) {
        float xv = x[w];
        size_t o0 = (size_t)w * DP1;
        out[OFF_STATE + o0] = xv;
        out[OFF_OWG   + o0] = xv;
        out[OFF_SA + o0 * TMOD + time] = xv;
        out[OFF_OG + o0 * TMOD + time] = ow[o0];
        v = fmaf(ow[o0], xv, v);
    }

    const int tia = posmod(time - 2 * DEPTH + 2 * (a + 1), TMOD);
    float sgv, rg, aprev;
    if (a < DEPTH - 1) {
        int t1 = (tia + 1) % TMOD;
        float rmv = sa_in[((size_t)w * DP1 + a + 2) * TMOD + t1];
        sgv = fmaf(rmv > 0.f ? 1.f : 0.f, g_contrib[k],
                   og_in[((size_t)w * DP1 + a + 1) * TMOD + tia]);
        rg = (sa_in[((size_t)w * DP1 + a + 1) * TMOD + tia] > 0.f) ? 1.f : 0.f;
        aprev = sa_in[((size_t)w * DP1 + a) * TMOD + posmod(tia - 1, TMOD)];
    } else {
        sgv = ow[(size_t)w * DP1 + DEPTH];
        rg = (s > 0.f) ? 1.f : 0.f;
        aprev = sa_in[((size_t)w * DP1 + DEPTH - 1) * TMOD + posmod(time - 1, TMOD)];
    }
    out[OFF_SG + k] = sgv;
    float mval = sgv * rg;
    g_m[k] = mval;
    if (k >= 3) g_mshift[k - 3] = mval;
    g_aprev[k] = aprev;

    __shared__ float red[8];
#pragma unroll
    for (int off = 16; off; off >>= 1)
        v += __shfl_down_sync(0xffffffffu, v, off);
    if ((threadIdx.x & 31) == 0) red[threadIdx.x >> 5] = v;
    __syncthreads();
    if (threadIdx.x == 0) {
        float t = 0.f;
#pragma unroll
        for (int i = 0; i < 8; ++i) t += red[i];
        atomicAdd(&g_out_acc, t);
    }
}

// ---------------------------------------------------------------------------
// grad: gradients[i,j,a] = aprev[i,a] * m[j,a]; block-per-row (round-8/11
// measured-best scheme), sector-aligned via mshift, streaming stores.
// ---------------------------------------------------------------------------
__global__ void k_grad(float* __restrict__ out) {
    const int i = blockIdx.x;
    const int tid = threadIdx.x;
    if (i == 0 && tid == 0) out[OFF_OUT] = g_out_acc;

    const float* ap = g_aprev + (size_t)i * 8;
    const float4 apv = (tid & 1)
        ? make_float4(__ldg(ap + 7), __ldg(ap + 0), __ldg(ap + 1), __ldg(ap + 2))
        : make_float4(__ldg(ap + 3), __ldg(ap + 4), __ldg(ap + 5), __ldg(ap + 6));

    float* dst = out + OFF_GRAD + (size_t)i * WD;
    const float4* ms4 = reinterpret_cast<const float4*>(g_mshift);

    for (int q = tid; q < NQ_GROW; q += 256) {
        float4 mv = ms4[q];
        __stcs(reinterpret_cast<float4*>(dst + 3 + 4 * q),
               make_float4(apv.x * mv.x, apv.y * mv.y,
                           apv.z * mv.z, apv.w * mv.w));
    }
    if (tid == 0) {
        dst[0] = __ldg(ap + 0) * g_m[0];
        dst[1] = __ldg(ap + 1) * g_m[1];
        dst[2] = __ldg(ap + 2) * g_m[2];
    } else if (tid == 1) {
        dst[WD - 1] = __ldg(ap + 7) * g_m[WD - 1];
    }
}

// ---------------------------------------------------------------------------
extern "C" void kernel_launch(void* const* d_in, const int* in_sizes, int n_in,
                              void* d_out, int out_size) {
    const float* x    = (const float*)d_in[0];
    const float* W    = (const float*)d_in[1];
    const float* ow   = (const float*)d_in[2];
    const float* st   = (const float*)d_in[3];
    const float* sa   = (const float*)d_in[4];
    const float* sgr  = (const float*)d_in[5];
    const float* og   = (const float*)d_in[6];
    const int*   tim  = (const int*)d_in[7];
    float* out = (float*)d_out;

    k_main<<<MAIN_BLK, 256>>>(W, st, sgr, out, sa, og);
    k_finalize<<<WD / 256, 256>>>(out, x, ow, sa, og, tim);
    k_grad<<<WIDTH, 256>>>(out);
}

// round 14
// speedup vs baseline: 1.0804x; 1.0250x over previous
#include <cuda_runtime.h>
#include <cstdint>
#include <cstddef>

#define WIDTH  2048
#define DEPTH  8
#define DP1    9
#define TMOD   242          // 30*DEPTH + 2
#define WD     16384        // WIDTH*DEPTH
#define NSPLIT 16           // i-splits for hidden
#define CHUNK  128          // WIDTH / NSPLIT
#define HBLK   256          // hidden blocks (16 kblk x 16 split)
#define WROLE  (HBLK + WIDTH)       // 2304 W-role blocks
#define MAIN_BLK (WROLE * 3)        // 6912: bx%3==0 -> W-role, else saog

// d_out layout (float32, reference return order)
#define OFF_OUT   0ULL
#define OFF_STATE 1ULL
#define OFF_SA    18433ULL
#define OFF_SG    4478977ULL
#define OFF_OG    4495361ULL
#define OFF_GRAD  8955905ULL
#define OFF_OWG   42510337ULL

#define N_SAOG    (WIDTH * DP1 * TMOD)     // 4460544
#define NQ_SAOG   1115135                  // quads idx = 3+4q
#define NQ_GROW   4095                     // per-row quads k = 3+4q

// scratch (allocation-free)
__device__ float g_hpart[NSPLIT][WD];     // hidden partials (1 MB)
__device__ float g_contrib[WD];           // contrib[i*8+a], a=0..6
__device__ float g_m[WD];
__device__ float g_mshift[WD];            // g_mshift[t] = m[t+3]
__device__ float g_aprev[WD];
__device__ float g_out_acc;

__device__ __forceinline__ int posmod(int v, int m) {
    int r = v % m;
    return r < 0 ? r + m : r;
}

// ---------------------------------------------------------------------------
// MAIN (round-13 structure, measured best): bx%3==0 -> W-role (wr<256 hidden,
// else contrib row wr-256); bx%3!=0 -> saog pure copy with __ldcs/__stcs so
// the copy stream doesn't thrash the W working set the reductions dedup on.
// ---------------------------------------------------------------------------
__global__ void k_main(const float* __restrict__ W,
                       const float* __restrict__ state_in,
                       const float* __restrict__ sgrad,
                       float* __restrict__ out,
                       const float* __restrict__ sa_in,
                       const float* __restrict__ og_in) {
    __shared__ float sh[CHUNK * 8];
    const int tid = threadIdx.x;
    const int bx  = blockIdx.x;

    if (bx % 3 == 0) {
        const int wr = bx / 3;             // 0..2303
        if (wr == 0 && tid == 0) g_out_acc = 0.f;

        if (wr < HBLK) {
            const int kblk  = wr & 15;
            const int split = wr >> 4;
            const int k4 = kblk * 1024 + tid * 4;
            const int i0 = split * CHUNK;
            const int dbase = (tid & 1) * 4;

            for (int idx = tid; idx < CHUNK * 8; idx += 256) {
                int i = idx >> 3, d = idx & 7;
                sh[idx] = state_in[(size_t)(i0 + i) * DP1 + d];
            }
            __syncthreads();

            const float* Wp = W + (size_t)i0 * WD + k4;
            float4 acc = make_float4(0.f, 0.f, 0.f, 0.f);
#pragma unroll 8
            for (int i = 0; i < CHUNK; ++i) {
                float4 w4 = *reinterpret_cast<const float4*>(Wp + (size_t)i * WD);
                float4 sv = *reinterpret_cast<const float4*>(&sh[i * 8 + dbase]);
                acc.x = fmaf(w4.x, sv.x, acc.x);
                acc.y = fmaf(w4.y, sv.y, acc.y);
                acc.z = fmaf(w4.z, sv.z, acc.z);
                acc.w = fmaf(w4.w, sv.w, acc.w);
            }
            *reinterpret_cast<float4*>(&g_hpart[split][k4]) = acc;
        } else {
            const int i = wr - HBLK;
            const float4* Wr = reinterpret_cast<const float4*>(W + (size_t)i * WD);
            const float4* gg = reinterpret_cast<const float4*>(sgrad);

            float acc[7] = {0, 0, 0, 0, 0, 0, 0};
            for (int j = tid; j < WIDTH; j += 256) {
                float4 w0 = Wr[j * 2];
                float4 w1 = Wr[j * 2 + 1];
                float4 g0 = gg[j * 2];
                float4 g1 = gg[j * 2 + 1];
                acc[0] = fmaf(w0.y, g0.y, acc[0]);
                acc[1] = fmaf(w0.z, g0.z, acc[1]);
                acc[2] = fmaf(w0.w, g0.w, acc[2]);
                acc[3] = fmaf(w1.x, g1.x, acc[3]);
                acc[4] = fmaf(w1.y, g1.y, acc[4]);
                acc[5] = fmaf(w1.z, g1.z, acc[5]);
                acc[6] = fmaf(w1.w, g1.w, acc[6]);
            }
            float (*red)[7] = reinterpret_cast<float (*)[7]>(sh);
#pragma unroll
            for (int a = 0; a < 7; ++a)
#pragma unroll
                for (int off = 16; off; off >>= 1)
                    acc[a] += __shfl_down_sync(0xffffffffu, acc[a], off);
            if ((tid & 31) == 0) {
                int w = tid >> 5;
#pragma unroll
                for (int a = 0; a < 7; ++a) red[w][a] = acc[a];
            }
            __syncthreads();
            if (tid < 7) {
                float s = 0.f;
#pragma unroll
                for (int w = 0; w < 8; ++w) s += red[w][tid];
                g_contrib[(size_t)i * 8 + tid] = s;
            }
        }
    } else {
        const int sid = bx - bx / 3 - 1;   // 0..4607
        const int q = sid * 256 + tid;
        if (q >= NQ_SAOG) return;
        const int idx = 3 + 4 * q;

        const float4* sa4 = reinterpret_cast<const float4*>(sa_in);
        const float4* og4 = reinterpret_cast<const float4*>(og_in);
        float4 sA = __ldcs(sa4 + q), sB = __ldcs(sa4 + q + 1);
        float4 oA = __ldcs(og4 + q), oB = __ldcs(og4 + q + 1);

        __stcs(reinterpret_cast<float4*>(&out[OFF_SA + idx]),
               make_float4(sA.w, sB.x, sB.y, sB.z));
        __stcs(reinterpret_cast<float4*>(&out[OFF_OG + idx]),
               make_float4(oA.w, oB.x, oB.y, oB.z));

        if (q == 0) {
#pragma unroll
            for (int e = 0; e < 3; ++e) {
                out[OFF_SA + e] = sa_in[e];
                out[OFF_OG + e] = og_in[e];
            }
        }
        if (q == NQ_SAOG - 1) {
            out[OFF_SA + N_SAOG - 1] = sa_in[N_SAOG - 1];
            out[OFF_OG + N_SAOG - 1] = og_in[N_SAOG - 1];
        }
    }
#if __CUDA_ARCH__ >= 900
    cudaTriggerProgrammaticLaunchCompletion();
#endif
}

// ---------------------------------------------------------------------------
// finalize (PDL secondary): PROLOGUE loads only harness inputs (sa/og/ow/x/
// time -> rm/rg/aprev/og terms), then gridDependencySynchronize, then the
// scratch reads (g_hpart/g_contrib) and ALL writes — incl. the SA/OG time-
// slice fixup, which must be ordered after k_main's saog stores.
// tia(a) = time + 2a - 14 (mod 242); tia==time only at a=7, (tia±1)!=time.
// ---------------------------------------------------------------------------
__global__ void k_finalize(float* __restrict__ out,
                           const float* __restrict__ x,
                           const float* __restrict__ ow,
                           const float* __restrict__ sa_in,
                           const float* __restrict__ og_in,
                           const int* __restrict__ time_p) {
    const int k = blockIdx.x * blockDim.x + threadIdx.x;   // 0..WD-1
    const int w = k >> 3, a = k & 7;
    const int time = *time_p;

    // ---- prologue: input-only loads ----
    const int tia = posmod(time - 2 * DEPTH + 2 * (a + 1), TMOD);
    float rm_v = 0.f, og_v = 0.f, rg_pre = 0.f, aprev;
    const float ow_o  = ow[(size_t)w * DP1 + a + 1];
    const float ow_o0 = (a == 0) ? ow[(size_t)w * DP1] : 0.f;
    const float xv    = (a == 0) ? x[w] : 0.f;
    if (a < DEPTH - 1) {
        int t1 = (tia + 1) % TMOD;
        rm_v = sa_in[((size_t)w * DP1 + a + 2) * TMOD + t1];
        og_v = og_in[((size_t)w * DP1 + a + 1) * TMOD + tia];
        rg_pre = sa_in[((size_t)w * DP1 + a + 1) * TMOD + tia];
        aprev = sa_in[((size_t)w * DP1 + a) * TMOD + posmod(tia - 1, TMOD)];
    } else {
        aprev = sa_in[((size_t)w * DP1 + DEPTH - 1) * TMOD + posmod(time - 1, TMOD)];
    }

#if __CUDA_ARCH__ >= 900
    cudaGridDependencySynchronize();
#endif

    // ---- consume k_main results ----
    float h = 0.f;
#pragma unroll
    for (int c = 0; c < NSPLIT; ++c) h += g_hpart[c][k];
    float s = fmaxf(h, 0.f);

    size_t o = (size_t)w * DP1 + a + 1;
    out[OFF_STATE + o] = s;
    out[OFF_OWG + o]   = s;
    out[OFF_SA + o * TMOD + time] = s;
    out[OFF_OG + o * TMOD + time] = ow_o;
    float v = ow_o * s;
    if (a == 0) {
        size_t o0 = (size_t)w * DP1;
        out[OFF_STATE + o0] = xv;
        out[OFF_OWG   + o0] = xv;
        out[OFF_SA + o0 * TMOD + time] = xv;
        out[OFF_OG + o0 * TMOD + time] = ow_o0;
        v = fmaf(ow_o0, xv, v);
    }

    float sgv, rg;
    if (a < DEPTH - 1) {
        sgv = fmaf(rm_v > 0.f ? 1.f : 0.f, g_contrib[k], og_v);
        rg = (rg_pre > 0.f) ? 1.f : 0.f;
    } else {
        sgv = ow[(size_t)w * DP1 + DEPTH];
        rg = (s > 0.f) ? 1.f : 0.f;
    }
    out[OFF_SG + k] = sgv;
    float mval = sgv * rg;
    g_m[k] = mval;
    if (k >= 3) g_mshift[k - 3] = mval;
    g_aprev[k] = aprev;

    __shared__ float red[8];
#pragma unroll
    for (int off = 16; off; off >>= 1)
        v += __shfl_down_sync(0xffffffffu, v, off);
    if ((threadIdx.x & 31) == 0) red[threadIdx.x >> 5] = v;
    __syncthreads();
    if (threadIdx.x == 0) {
        float t = 0.f;
#pragma unroll
        for (int i = 0; i < 8; ++i) t += red[i];
        atomicAdd(&g_out_acc, t);
    }
#if __CUDA_ARCH__ >= 900
    cudaTriggerProgrammaticLaunchCompletion();
#endif
}

// ---------------------------------------------------------------------------
// grad (PDL secondary): sync first (needs g_aprev/g_m/g_mshift/g_out_acc),
// block-per-row, sector-aligned via mshift, streaming stores.
// ---------------------------------------------------------------------------
__global__ void k_grad(float* __restrict__ out) {
    const int i = blockIdx.x;
    const int tid = threadIdx.x;

#if __CUDA_ARCH__ >= 900
    cudaGridDependencySynchronize();
#endif
    if (i == 0 && tid == 0) out[OFF_OUT] = g_out_acc;

    const float* ap = g_aprev + (size_t)i * 8;
    const float4 apv = (tid & 1)
        ? make_float4(__ldg(ap + 7), __ldg(ap + 0), __ldg(ap + 1), __ldg(ap + 2))
        : make_float4(__ldg(ap + 3), __ldg(ap + 4), __ldg(ap + 5), __ldg(ap + 6));

    float* dst = out + OFF_GRAD + (size_t)i * WD;
    const float4* ms4 = reinterpret_cast<const float4*>(g_mshift);

    for (int q = tid; q < NQ_GROW; q += 256) {
        float4 mv = ms4[q];
        __stcs(reinterpret_cast<float4*>(dst + 3 + 4 * q),
               make_float4(apv.x * mv.x, apv.y * mv.y,
                           apv.z * mv.z, apv.w * mv.w));
    }
    if (tid == 0) {
        dst[0] = __ldg(ap + 0) * g_m[0];
        dst[1] = __ldg(ap + 1) * g_m[1];
        dst[2] = __ldg(ap + 2) * g_m[2];
    } else if (tid == 1) {
        dst[WD - 1] = __ldg(ap + 7) * g_m[WD - 1];
    }
}

// ---------------------------------------------------------------------------
extern "C" void kernel_launch(void* const* d_in, const int* in_sizes, int n_in,
                              void* d_out, int out_size) {
    const float* x    = (const float*)d_in[0];
    const float* W    = (const float*)d_in[1];
    const float* ow   = (const float*)d_in[2];
    const float* st   = (const float*)d_in[3];
    const float* sa   = (const float*)d_in[4];
    const float* sgr  = (const float*)d_in[5];
    const float* og   = (const float*)d_in[6];
    const int*   tim  = (const int*)d_in[7];
    float* out = (float*)d_out;

    k_main<<<MAIN_BLK, 256>>>(W, st, sgr, out, sa, og);

    cudaLaunchAttribute attr[1];
    attr[0].id = cudaLaunchAttributeProgrammaticStreamSerialization;
    attr[0].val.programmaticStreamSerializationAllowed = 1;

    {
        cudaLaunchConfig_t cfg = {};
        cfg.gridDim = dim3(WD / 256);
        cfg.blockDim = dim3(256);
        cfg.attrs = attr;
        cfg.numAttrs = 1;
        cudaLaunchKernelEx(&cfg, k_finalize, out, x, ow, sa, og, tim);
    }
    {
        cudaLaunchConfig_t cfg = {};
        cfg.gridDim = dim3(WIDTH);
        cfg.blockDim = dim3(256);
        cfg.attrs = attr;
        cfg.numAttrs = 1;
        cudaLaunchKernelEx(&cfg, k_grad, out);
    }
}